// round 1
// baseline (speedup 1.0000x reference)
#include <cuda_runtime.h>
#include <cstdint>

#define Bn 128
#define Ln 1024
#define Hn 1024
#define Tn 9
#define NEG_INF (-3.0e38f)

// Emissions scratch: [b][l][t], 128*1024*9 floats = 4.7 MB
__device__ float g_emis[Bn * Ln * Tn];

// ---------------------------------------------------------------------------
// Kernel 1: emissions GEMM.  E[row][t] = dot(x[row,:1024], W[t,:1024]) + b[t]
// 8 warps/block, 4 rows/warp, W staged in shared (36 KB) reused across rows.
// ---------------------------------------------------------------------------
__global__ __launch_bounds__(256) void emit_kernel(
    const float* __restrict__ x, const float* __restrict__ W,
    const float* __restrict__ bias)
{
    __shared__ float Wsh[Tn][Hn];
    __shared__ float bsh[Tn];
    for (int i = threadIdx.x; i < Tn * Hn; i += 256)
        Wsh[i / Hn][i % Hn] = W[i];
    if (threadIdx.x < Tn) bsh[threadIdx.x] = bias[threadIdx.x];
    __syncthreads();

    const int warp = threadIdx.x >> 5;
    const int lane = threadIdx.x & 31;
    const int row0 = (blockIdx.x * 8 + warp) * 4;

    const float4* xr[4];
#pragma unroll
    for (int r = 0; r < 4; r++)
        xr[r] = (const float4*)(x + (size_t)(row0 + r) * Hn);

    float acc[4][Tn];
#pragma unroll
    for (int r = 0; r < 4; r++)
#pragma unroll
        for (int t = 0; t < Tn; t++) acc[r][t] = 0.f;

#pragma unroll 2
    for (int c = 0; c < 8; c++) {
        float4 v[4];
#pragma unroll
        for (int r = 0; r < 4; r++) v[r] = xr[r][lane + 32 * c];
        const int k = (lane + 32 * c) * 4;
#pragma unroll
        for (int t = 0; t < Tn; t++) {
            const float4 w = *(const float4*)&Wsh[t][k];
#pragma unroll
            for (int r = 0; r < 4; r++) {
                acc[r][t] += v[r].x * w.x;
                acc[r][t] += v[r].y * w.y;
                acc[r][t] += v[r].z * w.z;
                acc[r][t] += v[r].w * w.w;
            }
        }
    }

    // warp-wide butterfly reduce (36 independent sums)
#pragma unroll
    for (int o = 16; o; o >>= 1) {
#pragma unroll
        for (int r = 0; r < 4; r++)
#pragma unroll
            for (int t = 0; t < Tn; t++)
                acc[r][t] += __shfl_xor_sync(0xffffffffu, acc[r][t], o);
    }

    if (lane == 0) {
#pragma unroll
        for (int r = 0; r < 4; r++)
#pragma unroll
            for (int t = 0; t < Tn; t++)
                g_emis[(size_t)(row0 + r) * Tn + t] = acc[r][t] + bsh[t];
    }
}

// ---------------------------------------------------------------------------
// Kernel 2: Viterbi forward + backtrace, one warp per batch element.
// Lane j (j < 9) owns state j.  History in shared memory, backtrace in-kernel.
// ---------------------------------------------------------------------------
__global__ __launch_bounds__(32) void viterbi_kernel(
    const void* __restrict__ mask_raw,
    const float* __restrict__ startT, const float* __restrict__ endT,
    const float* __restrict__ trans,
    float* __restrict__ out)
{
    __shared__ uint8_t hist[Ln][12];  // backpointers for steps 1..L-1 (padded row)
    __shared__ uint8_t tags[Ln];

    const int b = blockIdx.x;
    const int lane = (int)threadIdx.x;
    const int j = lane;

    // ---- mask dtype detection + per-batch length (mask is a prefix mask) ----
    // mask[:,0] is all-true and lengths >= 512, so the first 32-bit word is:
    //   1           -> int32 storage
    //   0x3F800000  -> float32 storage (1.0f)
    //   0x01010101  -> 1-byte bool storage
    const unsigned* mw = (const unsigned*)mask_raw;
    const unsigned first = mw[0];
    const bool word_mask = (first == 1u) || (first == 0x3F800000u);
    int len = 0;
    if (word_mask) {
        const unsigned* m = mw + (size_t)b * Ln;
        for (int k = lane; k < Ln; k += 32) len += (m[k] != 0u);
    } else {
        const uint8_t* m = (const uint8_t*)mask_raw + (size_t)b * Ln;
        for (int k = lane; k < Ln; k += 32) len += (m[k] != 0);
    }
#pragma unroll
    for (int o = 16; o; o >>= 1) len += __shfl_xor_sync(0xffffffffu, len, o);

    const float* eb = g_emis + (size_t)b * Ln * Tn;

    float tcol[Tn];
    float score = NEG_INF;
    if (j < Tn) {
#pragma unroll
        for (int i = 0; i < Tn; i++) tcol[i] = trans[i * Tn + j];
        score = startT[j] + eb[j];
    } else {
#pragma unroll
        for (int i = 0; i < Tn; i++) tcol[i] = NEG_INF;
    }

    float e_cur = (j < Tn) ? __ldg(eb + Tn + j) : 0.f;

    for (int l = 1; l < Ln; l++) {
        // prefetch emissions a few lines ahead (idle lane)
        if (lane == 9) {
            const float* pf = eb + (size_t)min(l + 16, Ln - 1) * Tn;
            asm volatile("prefetch.global.L2 [%0];" ::"l"(pf));
        }
        float e_next = 0.f;
        if (l + 1 < Ln && j < Tn) e_next = __ldg(eb + (size_t)(l + 1) * Tn + j);

        float s[Tn];
#pragma unroll
        for (int i = 0; i < Tn; i++) s[i] = __shfl_sync(0xffffffffu, score, i);
        float cv[Tn];
#pragma unroll
        for (int i = 0; i < Tn; i++) cv[i] = s[i] + tcol[i];

        // max tree (depth 4)
        const float m0 = fmaxf(cv[0], cv[1]);
        const float m1 = fmaxf(cv[2], cv[3]);
        const float m2 = fmaxf(cv[4], cv[5]);
        const float m3 = fmaxf(cv[6], cv[7]);
        const float m4 = fmaxf(m0, m1);
        const float m5 = fmaxf(m2, m3);
        const float best = fmaxf(fmaxf(m4, m5), cv[8]);

        // first index attaining the max (exact fp equality; matches jnp.argmax)
        const int e0 = (cv[0] == best) ? 0 : 9;
        const int e1 = (cv[1] == best) ? 1 : 9;
        const int e2 = (cv[2] == best) ? 2 : 9;
        const int e3 = (cv[3] == best) ? 3 : 9;
        const int e4 = (cv[4] == best) ? 4 : 9;
        const int e5 = (cv[5] == best) ? 5 : 9;
        const int e6 = (cv[6] == best) ? 6 : 9;
        const int e7 = (cv[7] == best) ? 7 : 9;
        const int e8 = (cv[8] == best) ? 8 : 9;
        const int a0 = min(e0, e1);
        const int a1 = min(e2, e3);
        const int a2 = min(e4, e5);
        const int a3 = min(e6, e7);
        int bi = min(min(min(a0, a1), min(a2, a3)), e8);

        if (l < len) {
            score = best + e_cur;   // active step: advance score
        } else {
            bi = j;                 // frozen step: identity backpointer, score kept
        }
        if (j < Tn) hist[l][j] = (uint8_t)bi;
        e_cur = e_next;
    }

    // ---- final scores + argmax over states ----
    const float fin = (j < Tn) ? score + endT[j] : NEG_INF;
    float fv[Tn];
#pragma unroll
    for (int i = 0; i < Tn; i++) fv[i] = __shfl_sync(0xffffffffu, fin, i);
    const float f0 = fmaxf(fv[0], fv[1]);
    const float f1 = fmaxf(fv[2], fv[3]);
    const float f2 = fmaxf(fv[4], fv[5]);
    const float f3 = fmaxf(fv[6], fv[7]);
    const float best_f = fmaxf(fmaxf(fmaxf(f0, f1), fmaxf(f2, f3)), fv[8]);
    const int g0 = (fv[0] == best_f) ? 0 : 9;
    const int g1 = (fv[1] == best_f) ? 1 : 9;
    const int g2 = (fv[2] == best_f) ? 2 : 9;
    const int g3 = (fv[3] == best_f) ? 3 : 9;
    const int g4 = (fv[4] == best_f) ? 4 : 9;
    const int g5 = (fv[5] == best_f) ? 5 : 9;
    const int g6 = (fv[6] == best_f) ? 6 : 9;
    const int g7 = (fv[7] == best_f) ? 7 : 9;
    const int g8 = (fv[8] == best_f) ? 8 : 9;
    const int h0 = min(g0, g1);
    const int h1 = min(g2, g3);
    const int h2 = min(g4, g5);
    const int h3 = min(g6, g7);
    const int last_tag = min(min(min(h0, h1), min(h2, h3)), g8);

    if (lane == 0) {
        out[(size_t)Bn * Ln + b] = best_f;  // best_score
        int tag = last_tag;
        tags[Ln - 1] = (uint8_t)tag;
        for (int l = Ln - 2; l >= 0; --l) {
            tag = hist[l + 1][tag];
            tags[l] = (uint8_t)tag;
        }
    }
    __syncwarp();

    float* ot = out + (size_t)b * Ln;
    for (int k = lane; k < Ln; k += 32)
        ot[k] = (k < len) ? (float)tags[k] : 0.f;
}

// ---------------------------------------------------------------------------
extern "C" void kernel_launch(void* const* d_in, const int* in_sizes, int n_in,
                              void* d_out, int out_size)
{
    const float* x    = (const float*)d_in[0];  // encoder_output [B,L,H2]
    const void*  mask = d_in[1];                // mask [B,L]
    const float* W    = (const float*)d_in[2];  // [T,H2]
    const float* bias = (const float*)d_in[3];  // [T]
    const float* st   = (const float*)d_in[4];  // start_transitions [T]
    const float* en   = (const float*)d_in[5];  // end_transitions [T]
    const float* tr   = (const float*)d_in[6];  // transitions [T,T]
    float* out = (float*)d_out;                 // tags [B*L] then best_score [B]

    emit_kernel<<<(Bn * Ln) / 32, 256>>>(x, W, bias);
    viterbi_kernel<<<Bn, 32>>>(mask, st, en, tr, out);
}

// round 2
// speedup vs baseline: 1.2555x; 1.2555x over previous
#include <cuda_runtime.h>
#include <cstdint>

#define Bn 128
#define Ln 1024
#define Hn 1024
#define Tn 9
#define NEG_INF (-3.0e38f)

typedef unsigned long long u64;

// Emissions scratch: [b][l][t], 128*1024*9 floats = 4.7 MB (fits L2)
__device__ float g_emis[Bn * Ln * Tn];

// ---- f32x2 packed-FMA helpers (sm_103a FFMA2; only reachable via PTX) ----
__device__ __forceinline__ u64 ffma2(u64 a, u64 b, u64 c) {
    u64 d;
    asm("fma.rn.f32x2 %0, %1, %2, %3;" : "=l"(d) : "l"(a), "l"(b), "l"(c));
    return d;
}
__device__ __forceinline__ void upk(u64 v, float& lo, float& hi) {
    asm("mov.b64 {%0, %1}, %2;" : "=f"(lo), "=f"(hi) : "l"(v));
}

// ---------------------------------------------------------------------------
// Kernel 1: emissions GEMM.  E[row][t] = dot(x[row,:1024], W[t,:1024]) + b[t]
// 8 warps/block, 4 rows/warp, W staged in shared, f32x2 packed FMA.
// ---------------------------------------------------------------------------
__global__ __launch_bounds__(256, 2) void emit_kernel(
    const float* __restrict__ x, const float* __restrict__ W,
    const float* __restrict__ bias)
{
    __shared__ float Wsh[Tn][Hn];
    __shared__ float bsh[Tn];
    {
        const float4* Wg = (const float4*)W;
        float4* Ws = (float4*)&Wsh[0][0];
        for (int i = threadIdx.x; i < Tn * Hn / 4; i += 256) Ws[i] = Wg[i];
        if (threadIdx.x < Tn) bsh[threadIdx.x] = bias[threadIdx.x];
    }
    __syncthreads();

    const int warp = threadIdx.x >> 5;
    const int lane = threadIdx.x & 31;
    const int row0 = (blockIdx.x * 8 + warp) * 4;

    const ulonglong2* xr[4];
#pragma unroll
    for (int r = 0; r < 4; r++)
        xr[r] = (const ulonglong2*)(x + (size_t)(row0 + r) * Hn);

    u64 acc[4][Tn];
#pragma unroll
    for (int r = 0; r < 4; r++)
#pragma unroll
        for (int t = 0; t < Tn; t++) acc[r][t] = 0ull;

#pragma unroll 2
    for (int c = 0; c < 8; c++) {
        ulonglong2 v[4];
#pragma unroll
        for (int r = 0; r < 4; r++) v[r] = xr[r][lane + 32 * c];
        const int k = (lane + 32 * c) * 4;
#pragma unroll
        for (int t = 0; t < Tn; t++) {
            const ulonglong2 w = *(const ulonglong2*)&Wsh[t][k];
#pragma unroll
            for (int r = 0; r < 4; r++) {
                acc[r][t] = ffma2(v[r].x, w.x, acc[r][t]);
                acc[r][t] = ffma2(v[r].y, w.y, acc[r][t]);
            }
        }
    }

    // horizontal add of the packed pair, then warp butterfly reduce
    float res[4][Tn];
#pragma unroll
    for (int r = 0; r < 4; r++)
#pragma unroll
        for (int t = 0; t < Tn; t++) {
            float lo, hi;
            upk(acc[r][t], lo, hi);
            res[r][t] = lo + hi;
        }
#pragma unroll
    for (int o = 16; o; o >>= 1) {
#pragma unroll
        for (int r = 0; r < 4; r++)
#pragma unroll
            for (int t = 0; t < Tn; t++)
                res[r][t] += __shfl_xor_sync(0xffffffffu, res[r][t], o);
    }

    if (lane == 0) {
#pragma unroll
        for (int r = 0; r < 4; r++)
#pragma unroll
            for (int t = 0; t < Tn; t++)
                g_emis[(size_t)(row0 + r) * Tn + t] = res[r][t] + bsh[t];
    }
}

// ---------------------------------------------------------------------------
// Kernel 2: Viterbi forward + backtrace, one warp per batch element.
// Emissions staged in SMEM (removes L2 latency from the recurrence chain).
// Forward loop stops at len (frozen steps contribute nothing).
// ---------------------------------------------------------------------------
__global__ __launch_bounds__(32) void viterbi_kernel(
    const void* __restrict__ mask_raw,
    const float* __restrict__ startT, const float* __restrict__ endT,
    const float* __restrict__ trans,
    float* __restrict__ out)
{
    __shared__ float se[Ln * Tn + 40];      // staged emissions (+pad for lane over-read)
    __shared__ uint8_t hist[Ln * Tn + 16];  // backpointers, row stride 9
    __shared__ uint8_t tags[Ln];

    const int b = blockIdx.x;
    const int lane = (int)threadIdx.x;
    const int j = lane;

    // ---- stage emissions for this batch into SMEM (float4, from L2) ----
    {
        const float4* src = (const float4*)(g_emis + (size_t)b * Ln * Tn);
        float4* dst = (float4*)se;
        for (int i = lane; i < (Ln * Tn) / 4; i += 32) dst[i] = src[i];
    }

    // ---- mask dtype detection + per-batch length (prefix mask) ----
    const unsigned* mw = (const unsigned*)mask_raw;
    const unsigned first = mw[0];
    const bool word_mask = (first == 1u) || (first == 0x3F800000u);
    int len = 0;
    if (word_mask) {
        const unsigned* m = mw + (size_t)b * Ln;
        for (int k = lane; k < Ln; k += 32) len += (m[k] != 0u);
    } else {
        const uint8_t* m = (const uint8_t*)mask_raw + (size_t)b * Ln;
        for (int k = lane; k < Ln; k += 32) len += (m[k] != 0);
    }
#pragma unroll
    for (int o = 16; o; o >>= 1) len += __shfl_xor_sync(0xffffffffu, len, o);

    float tcol[Tn];
    if (j < Tn) {
#pragma unroll
        for (int i = 0; i < Tn; i++) tcol[i] = trans[i * Tn + j];
    } else {
#pragma unroll
        for (int i = 0; i < Tn; i++) tcol[i] = NEG_INF;
    }
    const float st = (j < Tn) ? startT[j] : 0.f;
    __syncwarp();  // staged emissions visible

    float score = (j < Tn) ? st + se[j] : NEG_INF;
    float e_cur = se[Tn + j];  // emission for step l=1 (pad covers lanes >= 9)

    for (int l = 1; l < len; l++) {
        const float e_next = se[(l + 1) * Tn + j];  // next step (pad covers overrun)

        float s[Tn];
#pragma unroll
        for (int i = 0; i < Tn; i++) s[i] = __shfl_sync(0xffffffffu, score, i);
        float cv[Tn];
#pragma unroll
        for (int i = 0; i < Tn; i++) cv[i] = s[i] + tcol[i];

        // max tree (depth 4)
        const float m0 = fmaxf(cv[0], cv[1]);
        const float m1 = fmaxf(cv[2], cv[3]);
        const float m2 = fmaxf(cv[4], cv[5]);
        const float m3 = fmaxf(cv[6], cv[7]);
        const float best = fmaxf(fmaxf(fmaxf(m0, m1), fmaxf(m2, m3)), cv[8]);

        score = best + e_cur;  // critical chain ends here

        // first index attaining the max (exact equality; matches jnp.argmax)
        const int e0 = (cv[0] == best) ? 0 : 9;
        const int e1 = (cv[1] == best) ? 1 : 9;
        const int e2 = (cv[2] == best) ? 2 : 9;
        const int e3 = (cv[3] == best) ? 3 : 9;
        const int e4 = (cv[4] == best) ? 4 : 9;
        const int e5 = (cv[5] == best) ? 5 : 9;
        const int e6 = (cv[6] == best) ? 6 : 9;
        const int e7 = (cv[7] == best) ? 7 : 9;
        const int e8 = (cv[8] == best) ? 8 : 9;
        const int a0 = min(min(e0, e1), min(e2, e3));
        const int a1 = min(min(e4, e5), min(e6, e7));
        const int bi = min(min(a0, a1), e8);

        if (j < Tn) hist[l * Tn + j] = (uint8_t)bi;
        e_cur = e_next;
    }

    // ---- final scores + argmax over states ----
    const float fin = (j < Tn) ? score + endT[j] : NEG_INF;
    float fv[Tn];
#pragma unroll
    for (int i = 0; i < Tn; i++) fv[i] = __shfl_sync(0xffffffffu, fin, i);
    const float f0 = fmaxf(fv[0], fv[1]);
    const float f1 = fmaxf(fv[2], fv[3]);
    const float f2 = fmaxf(fv[4], fv[5]);
    const float f3 = fmaxf(fv[6], fv[7]);
    const float best_f = fmaxf(fmaxf(fmaxf(f0, f1), fmaxf(f2, f3)), fv[8]);
    const int g0 = (fv[0] == best_f) ? 0 : 9;
    const int g1 = (fv[1] == best_f) ? 1 : 9;
    const int g2 = (fv[2] == best_f) ? 2 : 9;
    const int g3 = (fv[3] == best_f) ? 3 : 9;
    const int g4 = (fv[4] == best_f) ? 4 : 9;
    const int g5 = (fv[5] == best_f) ? 5 : 9;
    const int g6 = (fv[6] == best_f) ? 6 : 9;
    const int g7 = (fv[7] == best_f) ? 7 : 9;
    const int g8 = (fv[8] == best_f) ? 8 : 9;
    const int h0 = min(min(g0, g1), min(g2, g3));
    const int h1 = min(min(g4, g5), min(g6, g7));
    const int last_tag = min(min(h0, h1), g8);

    if (lane == 0) {
        out[(size_t)Bn * Ln + b] = best_f;  // best_score
        int tag = last_tag;
        tags[len - 1] = (uint8_t)tag;
        for (int l = len - 2; l >= 0; --l) {
            tag = hist[(l + 1) * Tn + tag];
            tags[l] = (uint8_t)tag;
        }
    }
    __syncwarp();

    float* ot = out + (size_t)b * Ln;
    for (int k = lane; k < Ln; k += 32)
        ot[k] = (k < len) ? (float)tags[k] : 0.f;
}

// ---------------------------------------------------------------------------
extern "C" void kernel_launch(void* const* d_in, const int* in_sizes, int n_in,
                              void* d_out, int out_size)
{
    const float* x    = (const float*)d_in[0];  // encoder_output [B,L,H2]
    const void*  mask = d_in[1];                // mask [B,L]
    const float* W    = (const float*)d_in[2];  // [T,H2]
    const float* bias = (const float*)d_in[3];  // [T]
    const float* st   = (const float*)d_in[4];  // start_transitions [T]
    const float* en   = (const float*)d_in[5];  // end_transitions [T]
    const float* tr   = (const float*)d_in[6];  // transitions [T,T]
    float* out = (float*)d_out;                 // tags [B*L] then best_score [B]

    emit_kernel<<<(Bn * Ln) / 32, 256>>>(x, W, bias);
    viterbi_kernel<<<Bn, 32>>>(mask, st, en, tr, out);
}

// round 3
// speedup vs baseline: 1.4109x; 1.1237x over previous
#include <cuda_runtime.h>
#include <cstdint>

#define Bn 128
#define Ln 1024
#define Hn 1024
#define Tn 9
#define NEG_INF (-3.0e38f)

typedef unsigned long long u64;

// Emissions scratch: [b][l][t], 128*1024*9 floats = 4.7 MB (fits L2)
__device__ float g_emis[Bn * Ln * Tn];

// ---- f32x2 packed-FMA helpers (sm_103a FFMA2; only reachable via PTX) ----
__device__ __forceinline__ u64 ffma2(u64 a, u64 b, u64 c) {
    u64 d;
    asm("fma.rn.f32x2 %0, %1, %2, %3;" : "=l"(d) : "l"(a), "l"(b), "l"(c));
    return d;
}
__device__ __forceinline__ void upk(u64 v, float& lo, float& hi) {
    asm("mov.b64 {%0, %1}, %2;" : "=f"(lo), "=f"(hi) : "l"(v));
}

#define EMIT_BLOCKS 296
#define NTILES ((Bn * Ln) / 32)  // 4096 tiles of 32 rows

// ---------------------------------------------------------------------------
// Kernel 1: emissions GEMM, persistent blocks.
// 8 warps/block, 4 rows/warp/tile. W read via LDG (L1-resident, x is __ldcs
// streaming so it doesn't evict W). Reduce via smem transpose (no shfl).
// ---------------------------------------------------------------------------
__global__ __launch_bounds__(256, 2) void emit_kernel(
    const float* __restrict__ x, const float* __restrict__ W,
    const float* __restrict__ bias)
{
    __shared__ float part[8][32][40];  // [warp][lane][36 sums], 40 KB

    const int warp = threadIdx.x >> 5;
    const int lane = threadIdx.x & 31;

    // per-lane epilogue constants: s = lane and s+32 (lanes 0..3)
    const float bias_a = bias[lane % Tn];
    const float bias_b = (lane < 4) ? bias[(lane + 32) % Tn] : 0.f;

    for (int tile = blockIdx.x; tile < NTILES; tile += EMIT_BLOCKS) {
        const int row0 = tile * 32 + warp * 4;

        const ulonglong2* xr[4];
#pragma unroll
        for (int r = 0; r < 4; r++)
            xr[r] = (const ulonglong2*)(x + (size_t)(row0 + r) * Hn);

        u64 acc[4][Tn];
#pragma unroll
        for (int r = 0; r < 4; r++)
#pragma unroll
            for (int t = 0; t < Tn; t++) acc[r][t] = 0ull;

#pragma unroll 2
        for (int c = 0; c < 8; c++) {
            ulonglong2 v[4];
#pragma unroll
            for (int r = 0; r < 4; r++) v[r] = __ldcs(&xr[r][lane + 32 * c]);
            const int k = (lane + 32 * c) * 4;
#pragma unroll
            for (int t = 0; t < Tn; t++) {
                const ulonglong2 w = *(const ulonglong2*)(W + t * Hn + k);
#pragma unroll
                for (int r = 0; r < 4; r++) {
                    acc[r][t] = ffma2(v[r].x, w.x, acc[r][t]);
                    acc[r][t] = ffma2(v[r].y, w.y, acc[r][t]);
                }
            }
        }

        // horizontal add of packed pair -> 36 per-lane partials
        float* pw = &part[warp][lane][0];
#pragma unroll
        for (int r = 0; r < 4; r++)
#pragma unroll
            for (int t = 0; t < Tn; t++) {
                float lo, hi;
                upk(acc[r][t], lo, hi);
                pw[r * Tn + t] = lo + hi;
            }
        __syncwarp();

        // transpose reduce: lane s sums its column over 32 lanes.
        // sum index s = r*9+t -> output g_emis[row0*9 + s] (coalesced).
        {
            float a0 = 0.f, a1 = 0.f, a2 = 0.f, a3 = 0.f;
#pragma unroll
            for (int L = 0; L < 32; L += 4) {
                a0 += part[warp][L + 0][lane];
                a1 += part[warp][L + 1][lane];
                a2 += part[warp][L + 2][lane];
                a3 += part[warp][L + 3][lane];
            }
            g_emis[(size_t)row0 * Tn + lane] = (a0 + a1) + (a2 + a3) + bias_a;
        }
        if (lane < 4) {
            const int s = lane + 32;
            float a0 = 0.f, a1 = 0.f, a2 = 0.f, a3 = 0.f;
#pragma unroll
            for (int L = 0; L < 32; L += 4) {
                a0 += part[warp][L + 0][s];
                a1 += part[warp][L + 1][s];
                a2 += part[warp][L + 2][s];
                a3 += part[warp][L + 3][s];
            }
            g_emis[(size_t)row0 * Tn + s] = (a0 + a1) + (a2 + a3) + bias_b;
        }
        __syncwarp();  // protect part[] before next tile overwrites
    }
}

// ---------------------------------------------------------------------------
// Kernel 2: Viterbi forward + backtrace, one warp per batch element.
// Score exchange via smem buffer (no SHFL). Emissions staged in SMEM.
// ---------------------------------------------------------------------------
__global__ __launch_bounds__(32) void viterbi_kernel(
    const void* __restrict__ mask_raw,
    const float* __restrict__ startT, const float* __restrict__ endT,
    const float* __restrict__ trans,
    float* __restrict__ out)
{
    __shared__ __align__(16) float se[Ln * Tn + 40];  // staged emissions
    __shared__ uint8_t hist[Ln * Tn + 16];            // backpointers
    __shared__ uint8_t tags[Ln];
    __shared__ __align__(16) float scb[32];           // score exchange buffer

    const int b = blockIdx.x;
    const int lane = (int)threadIdx.x;
    const int j = lane;

    // ---- stage emissions for this batch into SMEM ----
    {
        const float4* src = (const float4*)(g_emis + (size_t)b * Ln * Tn);
        float4* dst = (float4*)se;
        for (int i = lane; i < (Ln * Tn) / 4; i += 32) dst[i] = src[i];
    }

    // ---- mask dtype detection + per-batch length (prefix mask) ----
    const unsigned* mw = (const unsigned*)mask_raw;
    const unsigned first = mw[0];
    const bool word_mask = (first == 1u) || (first == 0x3F800000u);
    int len = 0;
    if (word_mask) {
        const unsigned* m = mw + (size_t)b * Ln;
        for (int k = lane; k < Ln; k += 32) len += (m[k] != 0u);
    } else {
        const uint8_t* m = (const uint8_t*)mask_raw + (size_t)b * Ln;
        for (int k = lane; k < Ln; k += 32) len += (m[k] != 0);
    }
#pragma unroll
    for (int o = 16; o; o >>= 1) len += __shfl_xor_sync(0xffffffffu, len, o);

    float tcol[Tn];
    if (j < Tn) {
#pragma unroll
        for (int i = 0; i < Tn; i++) tcol[i] = trans[i * Tn + j];
    } else {
#pragma unroll
        for (int i = 0; i < Tn; i++) tcol[i] = NEG_INF;
    }
    const float st = (j < Tn) ? startT[j] : 0.f;
    __syncwarp();  // staged emissions visible

    float score = (j < Tn) ? st + se[j] : NEG_INF;
    float e_cur = se[Tn + j];  // emission for step l=1 (pad covers lanes >= 9)

    for (int l = 1; l < len; l++) {
        // exchange scores via smem (warp-synchronous; converged warp)
        scb[lane] = score;
        asm volatile("" ::: "memory");
        const float4 sa = *(const float4*)&scb[0];
        const float4 sb = *(const float4*)&scb[4];
        const float s8v = scb[8];

        const float e_next = se[(l + 1) * Tn + j];

        const float cv0 = sa.x + tcol[0];
        const float cv1 = sa.y + tcol[1];
        const float cv2 = sa.z + tcol[2];
        const float cv3 = sa.w + tcol[3];
        const float cv4 = sb.x + tcol[4];
        const float cv5 = sb.y + tcol[5];
        const float cv6 = sb.z + tcol[6];
        const float cv7 = sb.w + tcol[7];
        const float cv8 = s8v + tcol[8];

        const float m0 = fmaxf(cv0, cv1);
        const float m1 = fmaxf(cv2, cv3);
        const float m2 = fmaxf(cv4, cv5);
        const float m3 = fmaxf(cv6, cv7);
        const float best = fmaxf(fmaxf(fmaxf(m0, m1), fmaxf(m2, m3)), cv8);

        score = best + e_cur;  // critical chain ends here

        // first index attaining the max (exact equality; matches jnp.argmax)
        const int e0 = (cv0 == best) ? 0 : 9;
        const int e1 = (cv1 == best) ? 1 : 9;
        const int e2 = (cv2 == best) ? 2 : 9;
        const int e3 = (cv3 == best) ? 3 : 9;
        const int e4 = (cv4 == best) ? 4 : 9;
        const int e5 = (cv5 == best) ? 5 : 9;
        const int e6 = (cv6 == best) ? 6 : 9;
        const int e7 = (cv7 == best) ? 7 : 9;
        const int e8 = (cv8 == best) ? 8 : 9;
        const int a0 = min(min(e0, e1), min(e2, e3));
        const int a1 = min(min(e4, e5), min(e6, e7));
        const int bi = min(min(a0, a1), e8);

        if (j < Tn) hist[l * Tn + j] = (uint8_t)bi;
        e_cur = e_next;
    }

    // ---- final scores + argmax over states (same smem exchange) ----
    const float fin = (j < Tn) ? score + endT[j] : NEG_INF;
    scb[lane] = fin;
    asm volatile("" ::: "memory");
    const float4 fa = *(const float4*)&scb[0];
    const float4 fb = *(const float4*)&scb[4];
    const float f8v = scb[8];
    const float f0 = fmaxf(fa.x, fa.y);
    const float f1 = fmaxf(fa.z, fa.w);
    const float f2 = fmaxf(fb.x, fb.y);
    const float f3 = fmaxf(fb.z, fb.w);
    const float best_f = fmaxf(fmaxf(fmaxf(f0, f1), fmaxf(f2, f3)), f8v);
    const int g0 = (fa.x == best_f) ? 0 : 9;
    const int g1 = (fa.y == best_f) ? 1 : 9;
    const int g2 = (fa.z == best_f) ? 2 : 9;
    const int g3 = (fa.w == best_f) ? 3 : 9;
    const int g4 = (fb.x == best_f) ? 4 : 9;
    const int g5 = (fb.y == best_f) ? 5 : 9;
    const int g6 = (fb.z == best_f) ? 6 : 9;
    const int g7 = (fb.w == best_f) ? 7 : 9;
    const int g8 = (f8v == best_f) ? 8 : 9;
    const int h0 = min(min(g0, g1), min(g2, g3));
    const int h1 = min(min(g4, g5), min(g6, g7));
    const int last_tag = min(min(h0, h1), g8);

    if (lane == 0) {
        out[(size_t)Bn * Ln + b] = best_f;  // best_score
        int tag = last_tag;
        tags[len - 1] = (uint8_t)tag;
        for (int l = len - 2; l >= 0; --l) {
            tag = hist[(l + 1) * Tn + tag];
            tags[l] = (uint8_t)tag;
        }
    }
    __syncwarp();

    float* ot = out + (size_t)b * Ln;
    for (int k = lane; k < Ln; k += 32)
        ot[k] = (k < len) ? (float)tags[k] : 0.f;
}

// ---------------------------------------------------------------------------
extern "C" void kernel_launch(void* const* d_in, const int* in_sizes, int n_in,
                              void* d_out, int out_size)
{
    const float* x    = (const float*)d_in[0];  // encoder_output [B,L,H2]
    const void*  mask = d_in[1];                // mask [B,L]
    const float* W    = (const float*)d_in[2];  // [T,H2]
    const float* bias = (const float*)d_in[3];  // [T]
    const float* st   = (const float*)d_in[4];  // start_transitions [T]
    const float* en   = (const float*)d_in[5];  // end_transitions [T]
    const float* tr   = (const float*)d_in[6];  // transitions [T,T]
    float* out = (float*)d_out;                 // tags [B*L] then best_score [B]

    emit_kernel<<<EMIT_BLOCKS, 256>>>(x, W, bias);
    viterbi_kernel<<<Bn, 32>>>(mask, st, en, tr, out);
}

// round 4
// speedup vs baseline: 1.5201x; 1.0774x over previous
#include <cuda_runtime.h>
#include <cstdint>

#define Bn 128
#define Ln 1024
#define Hn 1024
#define Tn 9
#define NEG_INF (-3.0e38f)

typedef unsigned long long u64;

// ---- f32x2 packed-FMA helpers (sm_103a FFMA2; only reachable via PTX) ----
__device__ __forceinline__ u64 ffma2(u64 a, u64 b, u64 c) {
    u64 d;
    asm("fma.rn.f32x2 %0, %1, %2, %3;" : "=l"(d) : "l"(a), "l"(b), "l"(c));
    return d;
}
__device__ __forceinline__ void upk(u64 v, float& lo, float& hi) {
    asm("mov.b64 {%0, %1}, %2;" : "=f"(lo), "=f"(hi) : "l"(v));
}

// dynamic smem: se = float[Ln*Tn + 40], then hist = u32[Ln*12]
#define SE_F (Ln * Tn + 40)
#define DYN_BYTES (SE_F * 4 + Ln * 12 * 4)

// ---------------------------------------------------------------------------
// Fused kernel: one block per batch. 8 warps compute emissions into SMEM,
// then warp 0 runs branch-free Viterbi + backtrace, block writes tags.
// ---------------------------------------------------------------------------
__global__ __launch_bounds__(256, 1) void fused_kernel(
    const float* __restrict__ x, const void* __restrict__ mask_raw,
    const float* __restrict__ W, const float* __restrict__ bias,
    const float* __restrict__ startT, const float* __restrict__ endT,
    const float* __restrict__ trans, float* __restrict__ out)
{
    extern __shared__ __align__(16) float dyn[];
    float* se = dyn;                               // emissions [Ln][Tn] (+pad)
    unsigned* hist = (unsigned*)(dyn + SE_F);      // backpointers [Ln][12]

    __shared__ float part[8][32][40];              // per-warp reduce scratch
    __shared__ uint8_t tags[Ln];
    __shared__ __align__(16) float scb[32];
    __shared__ int s_len;
    __shared__ float s_best;

    const int b = blockIdx.x;
    const int warp = threadIdx.x >> 5;
    const int lane = threadIdx.x & 31;

    // =============================== emit phase ===============================
    // E[l][t] = dot(x[b,l,:], W[t,:]) + bias[t], written to se[l*9+t].
    const float bias_a = bias[lane % Tn];
    const float bias_b = bias[(lane + 32) % Tn];   // used by lanes < 4

    for (int g = 0; g < 32; g++) {
        const int row0 = g * 32 + warp * 4;        // local row within batch

        const ulonglong2* xr[4];
#pragma unroll
        for (int r = 0; r < 4; r++)
            xr[r] = (const ulonglong2*)(x + ((size_t)b * Ln + row0 + r) * Hn);

        u64 acc[4][Tn];
#pragma unroll
        for (int r = 0; r < 4; r++)
#pragma unroll
            for (int t = 0; t < Tn; t++) acc[r][t] = 0ull;

#pragma unroll 2
        for (int c = 0; c < 8; c++) {
            ulonglong2 v[4];
#pragma unroll
            for (int r = 0; r < 4; r++) v[r] = __ldcs(&xr[r][lane + 32 * c]);
            const int k = (lane + 32 * c) * 4;
#pragma unroll
            for (int t = 0; t < Tn; t++) {
                const ulonglong2 w = *(const ulonglong2*)(W + t * Hn + k);
#pragma unroll
                for (int r = 0; r < 4; r++) {
                    acc[r][t] = ffma2(v[r].x, w.x, acc[r][t]);
                    acc[r][t] = ffma2(v[r].y, w.y, acc[r][t]);
                }
            }
        }

        // horizontal add of packed pair -> 36 per-lane partials
        float* pw = &part[warp][lane][0];
#pragma unroll
        for (int r = 0; r < 4; r++)
#pragma unroll
            for (int t = 0; t < Tn; t++) {
                float lo, hi;
                upk(acc[r][t], lo, hi);
                pw[r * Tn + t] = lo + hi;
            }
        __syncwarp();

        // transpose reduce: lane s sums column s (s = r*9+t) over 32 lanes
        {
            float a0 = 0.f, a1 = 0.f, a2 = 0.f, a3 = 0.f;
#pragma unroll
            for (int L = 0; L < 32; L += 4) {
                a0 += part[warp][L + 0][lane];
                a1 += part[warp][L + 1][lane];
                a2 += part[warp][L + 2][lane];
                a3 += part[warp][L + 3][lane];
            }
            se[row0 * Tn + lane] = (a0 + a1) + (a2 + a3) + bias_a;
        }
        if (lane < 4) {
            const int s = lane + 32;
            float a0 = 0.f, a1 = 0.f, a2 = 0.f, a3 = 0.f;
#pragma unroll
            for (int L = 0; L < 32; L += 4) {
                a0 += part[warp][L + 0][s];
                a1 += part[warp][L + 1][s];
                a2 += part[warp][L + 2][s];
                a3 += part[warp][L + 3][s];
            }
            se[row0 * Tn + s] = (a0 + a1) + (a2 + a3) + bias_b;
        }
        __syncwarp();  // protect part[] before next tile overwrites
    }
    __syncthreads();   // emissions visible to warp 0

    // ============================== viterbi phase =============================
    if (warp == 0) {
        const int j = lane;

        // mask dtype detection + length (prefix mask; mask[:,0] all true)
        const unsigned* mw = (const unsigned*)mask_raw;
        const unsigned first = mw[0];
        const bool word_mask = (first == 1u) || (first == 0x3F800000u);
        int len = 0;
        if (word_mask) {
            const unsigned* m = mw + (size_t)b * Ln;
            for (int k = lane; k < Ln; k += 32) len += (m[k] != 0u);
        } else {
            const uint8_t* m = (const uint8_t*)mask_raw + (size_t)b * Ln;
            for (int k = lane; k < Ln; k += 32) len += (m[k] != 0);
        }
#pragma unroll
        for (int o = 16; o; o >>= 1) len += __shfl_xor_sync(0xffffffffu, len, o);

        // per-lane constants (hoisted; loop body is branch-free)
        const int jc = (j < Tn) ? j : 8;      // clamped for safe trans reads
        const int hidx = (j < 11) ? j : 11;   // hist slot (lanes>=9 -> garbage slot)
        float tcol[Tn];
#pragma unroll
        for (int i = 0; i < Tn; i++) tcol[i] = trans[i * Tn + jc];
        float score = (j < Tn) ? startT[j] + se[j] : NEG_INF;

        float e_cur = se[Tn + j];             // emission for step l=1 (pad ok)
        const float* ep = se + 2 * Tn;        // -> se[(l+1)*9] at l=1
        unsigned* hp = hist + 12;             // -> hist row l=1

        for (int l = 1; l < len; l++) {
            // exchange scores via smem (warp-synchronous, converged warp)
            scb[lane] = score;
            asm volatile("" ::: "memory");
            const float4 sa = *(const float4*)&scb[0];
            const float4 sb = *(const float4*)&scb[4];
            const float s8v = scb[8];
            const float e_next = ep[j];

            const float cv0 = sa.x + tcol[0];
            const float cv1 = sa.y + tcol[1];
            const float cv2 = sa.z + tcol[2];
            const float cv3 = sa.w + tcol[3];
            const float cv4 = sb.x + tcol[4];
            const float cv5 = sb.y + tcol[5];
            const float cv6 = sb.z + tcol[6];
            const float cv7 = sb.w + tcol[7];
            const float cv8 = s8v + tcol[8];

            const float m0 = fmaxf(cv0, cv1);
            const float m1 = fmaxf(cv2, cv3);
            const float m2 = fmaxf(cv4, cv5);
            const float m3 = fmaxf(cv6, cv7);
            const float best = fmaxf(fmaxf(fmaxf(m0, m1), fmaxf(m2, m3)), cv8);

            score = best + e_cur;  // critical chain ends here

            // first index attaining max (exact equality; matches jnp.argmax)
            const int e0 = (cv0 == best) ? 0 : 9;
            const int e1 = (cv1 == best) ? 1 : 9;
            const int e2 = (cv2 == best) ? 2 : 9;
            const int e3 = (cv3 == best) ? 3 : 9;
            const int e4 = (cv4 == best) ? 4 : 9;
            const int e5 = (cv5 == best) ? 5 : 9;
            const int e6 = (cv6 == best) ? 6 : 9;
            const int e7 = (cv7 == best) ? 7 : 9;
            const int e8 = (cv8 == best) ? 8 : 9;
            const int a0 = min(min(e0, e1), min(e2, e3));
            const int a1 = min(min(e4, e5), min(e6, e7));
            const int bi = min(min(a0, a1), e8);

            hp[hidx] = (unsigned)bi;   // unconditional: no BSSY/BSYNC
            ep += Tn;
            hp += 12;
            e_cur = e_next;
        }

        // final scores + argmax over states
        const float fin = (j < Tn) ? score + endT[j] : NEG_INF;
        scb[lane] = fin;
        asm volatile("" ::: "memory");
        const float4 fa = *(const float4*)&scb[0];
        const float4 fb = *(const float4*)&scb[4];
        const float f8v = scb[8];
        const float f0 = fmaxf(fa.x, fa.y);
        const float f1 = fmaxf(fa.z, fa.w);
        const float f2 = fmaxf(fb.x, fb.y);
        const float f3 = fmaxf(fb.z, fb.w);
        const float best_f = fmaxf(fmaxf(fmaxf(f0, f1), fmaxf(f2, f3)), f8v);
        const int g0 = (fa.x == best_f) ? 0 : 9;
        const int g1 = (fa.y == best_f) ? 1 : 9;
        const int g2 = (fa.z == best_f) ? 2 : 9;
        const int g3 = (fa.w == best_f) ? 3 : 9;
        const int g4 = (fb.x == best_f) ? 4 : 9;
        const int g5 = (fb.y == best_f) ? 5 : 9;
        const int g6 = (fb.z == best_f) ? 6 : 9;
        const int g7 = (fb.w == best_f) ? 7 : 9;
        const int g8 = (f8v == best_f) ? 8 : 9;
        const int h0 = min(min(g0, g1), min(g2, g3));
        const int h1 = min(min(g4, g5), min(g6, g7));
        const int last_tag = min(min(h0, h1), g8);

        if (lane == 0) {
            s_len = len;
            s_best = best_f;
            int tag = last_tag;
            tags[len - 1] = (uint8_t)tag;
            for (int l = len - 2; l >= 0; --l) {
                tag = (int)hist[(l + 1) * 12 + tag];
                tags[l] = (uint8_t)tag;
            }
        }
    }
    __syncthreads();

    // =============================== write out ================================
    const int len = s_len;
    float* ot = out + (size_t)b * Ln;
    for (int k = threadIdx.x; k < Ln; k += 256)
        ot[k] = (k < len) ? (float)tags[k] : 0.f;
    if (threadIdx.x == 0) out[(size_t)Bn * Ln + b] = s_best;
}

// ---------------------------------------------------------------------------
extern "C" void kernel_launch(void* const* d_in, const int* in_sizes, int n_in,
                              void* d_out, int out_size)
{
    const float* x    = (const float*)d_in[0];  // encoder_output [B,L,H2]
    const void*  mask = d_in[1];                // mask [B,L]
    const float* W    = (const float*)d_in[2];  // [T,H2]
    const float* bias = (const float*)d_in[3];  // [T]
    const float* st   = (const float*)d_in[4];  // start_transitions [T]
    const float* en   = (const float*)d_in[5];  // end_transitions [T]
    const float* tr   = (const float*)d_in[6];  // transitions [T,T]
    float* out = (float*)d_out;                 // tags [B*L] then best_score [B]

    cudaFuncSetAttribute(fused_kernel,
                         cudaFuncAttributeMaxDynamicSharedMemorySize, DYN_BYTES);
    fused_kernel<<<Bn, 256, DYN_BYTES>>>(x, mask, W, bias, st, en, tr, out);
}

// round 5
// speedup vs baseline: 1.9307x; 1.2701x over previous
#include <cuda_runtime.h>
#include <cstdint>

#define Bn 128
#define Ln 1024
#define Hn 1024
#define Tn 9
#define NEG_INF (-3.0e38f)

typedef unsigned long long u64;

// ---- f32x2 packed-FMA helpers (sm_103a FFMA2; only reachable via PTX) ----
__device__ __forceinline__ u64 ffma2(u64 a, u64 b, u64 c) {
    u64 d;
    asm("fma.rn.f32x2 %0, %1, %2, %3;" : "=l"(d) : "l"(a), "l"(b), "l"(c));
    return d;
}
__device__ __forceinline__ void upk(u64 v, float& lo, float& hi) {
    asm("mov.b64 {%0, %1}, %2;" : "=f"(lo), "=f"(hi) : "l"(v));
}

// dynamic smem: se = float[Ln*12 + 64] (emissions, overwritten by score vecs),
//               hist8 = uint8[Ln*16]
#define SE_F (Ln * 12 + 64)
#define DYN_BYTES (SE_F * 4 + Ln * 16)

// ---------------------------------------------------------------------------
// Fused kernel: one block per batch.
//   Phase A: 8 warps compute emissions into SMEM (double-buffered x loads).
//   Phase B: warp 0 runs slim Viterbi forward (no argmax), score vectors
//            overwrite consumed emission rows.
//   Phase C: all 256 threads compute backpointers in parallel from the
//            stored score vectors (bit-identical FADD/fmax values).
//   Phase D: thread 0 backtraces; block writes tags.
// ---------------------------------------------------------------------------
__global__ __launch_bounds__(256, 1) void fused_kernel(
    const float* __restrict__ x, const void* __restrict__ mask_raw,
    const float* __restrict__ W, const float* __restrict__ bias,
    const float* __restrict__ startT, const float* __restrict__ endT,
    const float* __restrict__ trans, float* __restrict__ out)
{
    extern __shared__ __align__(16) float dyn[];
    float* se = dyn;                                // [Ln][12] emissions / score vecs
    uint8_t* hist8 = (uint8_t*)(dyn + SE_F);        // [Ln][16] backpointers

    __shared__ float part[8][32][40];               // per-warp reduce scratch
    __shared__ float ttr[Tn * Tn];                  // transitions
    __shared__ uint8_t tags[Ln];
    __shared__ int s_len, s_lasttag;
    __shared__ float s_best;

    const int b = blockIdx.x;
    const int warp = threadIdx.x >> 5;
    const int lane = threadIdx.x & 31;

    if (threadIdx.x < Tn * Tn) ttr[threadIdx.x] = trans[threadIdx.x];

    // =============================== Phase A: emit ===========================
    // E[l][t] = dot(x[b,l,:], W[t,:]) + bias[t] -> se[l*12 + t]
    const float bias_a = bias[lane % Tn];
    const float bias_b = bias[(lane + 32) % Tn];    // lanes < 4
    // destination offsets for stride-12 rows (s -> (s/9)*12 + s%9)
    const int dst_a = (lane / 9) * 12 + (lane % 9);
    const int dst_b = ((lane + 32) / 9) * 12 + ((lane + 32) % 9);

    const ulonglong2* X = (const ulonglong2*)(x + (size_t)b * Ln * Hn);

    ulonglong2 va[4], vb[4];
    {   // preload tile 0, c = 0
        const int row0 = warp * 4;
#pragma unroll
        for (int r = 0; r < 4; r++) va[r] = __ldcs(X + (row0 + r) * 256 + lane);
    }

    for (int g = 0; g < 32; g++) {
        const int row0 = g * 32 + warp * 4;
        const int row0n = (g < 31) ? row0 + 32 : row0;  // next tile (clamped)

        u64 acc[4][Tn];
#pragma unroll
        for (int r = 0; r < 4; r++)
#pragma unroll
            for (int t = 0; t < Tn; t++) acc[r][t] = 0ull;

#pragma unroll
        for (int c = 0; c < 8; c += 2) {
            // prefetch c+1 into vb, compute va (chunk c)
#pragma unroll
            for (int r = 0; r < 4; r++)
                vb[r] = __ldcs(X + (row0 + r) * 256 + lane + 32 * (c + 1));
            {
                const int k = (lane + 32 * c) * 4;
#pragma unroll
                for (int t = 0; t < Tn; t++) {
                    const ulonglong2 w = *(const ulonglong2*)(W + t * Hn + k);
#pragma unroll
                    for (int r = 0; r < 4; r++) {
                        acc[r][t] = ffma2(va[r].x, w.x, acc[r][t]);
                        acc[r][t] = ffma2(va[r].y, w.y, acc[r][t]);
                    }
                }
            }
            // prefetch c+2 (or next tile's c=0) into va, compute vb (chunk c+1)
            const int cn = (c + 2 < 8) ? (c + 2) : 0;
            const int rown = (c + 2 < 8) ? row0 : row0n;
#pragma unroll
            for (int r = 0; r < 4; r++)
                va[r] = __ldcs(X + (rown + r) * 256 + lane + 32 * cn);
            {
                const int k = (lane + 32 * (c + 1)) * 4;
#pragma unroll
                for (int t = 0; t < Tn; t++) {
                    const ulonglong2 w = *(const ulonglong2*)(W + t * Hn + k);
#pragma unroll
                    for (int r = 0; r < 4; r++) {
                        acc[r][t] = ffma2(vb[r].x, w.x, acc[r][t]);
                        acc[r][t] = ffma2(vb[r].y, w.y, acc[r][t]);
                    }
                }
            }
        }

        // horizontal add of packed pair -> 36 per-lane partials
        float* pw = &part[warp][lane][0];
#pragma unroll
        for (int r = 0; r < 4; r++)
#pragma unroll
            for (int t = 0; t < Tn; t++) {
                float lo, hi;
                upk(acc[r][t], lo, hi);
                pw[r * Tn + t] = lo + hi;
            }
        __syncwarp();

        // transpose reduce: lane s sums column s (s = r*9+t) over 32 lanes
        {
            float a0 = 0.f, a1 = 0.f, a2 = 0.f, a3 = 0.f;
#pragma unroll
            for (int L = 0; L < 32; L += 4) {
                a0 += part[warp][L + 0][lane];
                a1 += part[warp][L + 1][lane];
                a2 += part[warp][L + 2][lane];
                a3 += part[warp][L + 3][lane];
            }
            se[row0 * 12 + dst_a] = (a0 + a1) + (a2 + a3) + bias_a;
        }
        if (lane < 4) {
            const int s = lane + 32;
            float a0 = 0.f, a1 = 0.f, a2 = 0.f, a3 = 0.f;
#pragma unroll
            for (int L = 0; L < 32; L += 4) {
                a0 += part[warp][L + 0][s];
                a1 += part[warp][L + 1][s];
                a2 += part[warp][L + 2][s];
                a3 += part[warp][L + 3][s];
            }
            se[row0 * 12 + dst_b] = (a0 + a1) + (a2 + a3) + bias_b;
        }
        __syncwarp();
    }
    __syncthreads();

    // ======================= Phase B: forward (warp 0) =======================
    if (warp == 0) {
        const int j = lane;

        // mask dtype detection + length (prefix mask)
        const unsigned* mw = (const unsigned*)mask_raw;
        const unsigned first = mw[0];
        const bool word_mask = (first == 1u) || (first == 0x3F800000u);
        int len = 0;
        if (word_mask) {
            const unsigned* m = mw + (size_t)b * Ln;
            for (int k = lane; k < Ln; k += 32) len += (m[k] != 0u);
        } else {
            const uint8_t* m = (const uint8_t*)mask_raw + (size_t)b * Ln;
            for (int k = lane; k < Ln; k += 32) len += (m[k] != 0);
        }
#pragma unroll
        for (int o = 16; o; o >>= 1) len += __shfl_xor_sync(0xffffffffu, len, o);

        const int jc = (j < Tn) ? j : 8;
        const int hidx = (j < 11) ? j : 11;  // lanes >= 9 land in pad cols 9..11
        float tcol[Tn];
#pragma unroll
        for (int i = 0; i < Tn; i++) tcol[i] = ttr[i * Tn + jc];

        float score = (j < Tn) ? startT[j] + se[j] : NEG_INF;

        const float* erow = se + 12;  // emission row l (starts at l=1)
        float* srow = se;             // score-vector row l-1

        for (int l = 1; l < len; l++) {
            srow[hidx] = score;  // store sv_{l-1} over consumed emission row
            asm volatile("" ::: "memory");
            const float4 sa = *(const float4*)(srow);
            const float4 sb = *(const float4*)(srow + 4);
            const float s8v = srow[8];
            const float e = erow[j];  // emission[l][j] (pad-safe for lanes>=9)

            const float cv0 = sa.x + tcol[0];
            const float cv1 = sa.y + tcol[1];
            const float cv2 = sa.z + tcol[2];
            const float cv3 = sa.w + tcol[3];
            const float cv4 = sb.x + tcol[4];
            const float cv5 = sb.y + tcol[5];
            const float cv6 = sb.z + tcol[6];
            const float cv7 = sb.w + tcol[7];
            const float cv8 = s8v + tcol[8];

            const float m0 = fmaxf(cv0, cv1);
            const float m1 = fmaxf(cv2, cv3);
            const float m2 = fmaxf(cv4, cv5);
            const float m3 = fmaxf(cv6, cv7);
            const float best = fmaxf(fmaxf(fmaxf(m0, m1), fmaxf(m2, m3)), cv8);

            score = best + e;
            srow += 12;
            erow += 12;
        }

        // final scores + argmax over states (exchange via row len-1)
        const float fin = (j < Tn) ? score + endT[j] : NEG_INF;
        srow[hidx] = fin;  // srow now = row len-1 (consumed)
        asm volatile("" ::: "memory");
        const float4 fa = *(const float4*)(srow);
        const float4 fb = *(const float4*)(srow + 4);
        const float f8v = srow[8];
        const float f0 = fmaxf(fa.x, fa.y);
        const float f1 = fmaxf(fa.z, fa.w);
        const float f2 = fmaxf(fb.x, fb.y);
        const float f3 = fmaxf(fb.z, fb.w);
        const float best_f = fmaxf(fmaxf(fmaxf(f0, f1), fmaxf(f2, f3)), f8v);
        const int g0 = (fa.x == best_f) ? 0 : 9;
        const int g1 = (fa.y == best_f) ? 1 : 9;
        const int g2 = (fa.z == best_f) ? 2 : 9;
        const int g3 = (fa.w == best_f) ? 3 : 9;
        const int g4 = (fb.x == best_f) ? 4 : 9;
        const int g5 = (fb.y == best_f) ? 5 : 9;
        const int g6 = (fb.z == best_f) ? 6 : 9;
        const int g7 = (fb.w == best_f) ? 7 : 9;
        const int g8 = (f8v == best_f) ? 8 : 9;
        const int h0 = min(min(g0, g1), min(g2, g3));
        const int h1 = min(min(g4, g5), min(g6, g7));
        if (lane == 0) {
            s_len = len;
            s_best = best_f;
            s_lasttag = min(min(h0, h1), g8);
        }
    }
    __syncthreads();

    // ================= Phase C: parallel backpointers (all threads) ==========
    const int len = s_len;
    for (int l = 1 + (int)threadIdx.x; l < len; l += 256) {
        const float* sv = se + (l - 1) * 12;
        const float s0 = sv[0], s1 = sv[1], s2 = sv[2], s3 = sv[3], s4 = sv[4];
        const float s5 = sv[5], s6 = sv[6], s7 = sv[7], s8 = sv[8];
#pragma unroll
        for (int j = 0; j < Tn; j++) {
            const float cv0 = s0 + ttr[0 * Tn + j];
            const float cv1 = s1 + ttr[1 * Tn + j];
            const float cv2 = s2 + ttr[2 * Tn + j];
            const float cv3 = s3 + ttr[3 * Tn + j];
            const float cv4 = s4 + ttr[4 * Tn + j];
            const float cv5 = s5 + ttr[5 * Tn + j];
            const float cv6 = s6 + ttr[6 * Tn + j];
            const float cv7 = s7 + ttr[7 * Tn + j];
            const float cv8 = s8 + ttr[8 * Tn + j];
            const float m0 = fmaxf(cv0, cv1);
            const float m1 = fmaxf(cv2, cv3);
            const float m2 = fmaxf(cv4, cv5);
            const float m3 = fmaxf(cv6, cv7);
            const float best = fmaxf(fmaxf(fmaxf(m0, m1), fmaxf(m2, m3)), cv8);
            const int e0 = (cv0 == best) ? 0 : 9;
            const int e1 = (cv1 == best) ? 1 : 9;
            const int e2 = (cv2 == best) ? 2 : 9;
            const int e3 = (cv3 == best) ? 3 : 9;
            const int e4 = (cv4 == best) ? 4 : 9;
            const int e5 = (cv5 == best) ? 5 : 9;
            const int e6 = (cv6 == best) ? 6 : 9;
            const int e7 = (cv7 == best) ? 7 : 9;
            const int e8 = (cv8 == best) ? 8 : 9;
            const int a0 = min(min(e0, e1), min(e2, e3));
            const int a1 = min(min(e4, e5), min(e6, e7));
            hist8[l * 16 + j] = (uint8_t)min(min(a0, a1), e8);
        }
    }
    __syncthreads();

    // ===================== Phase D: backtrace (thread 0) =====================
    if (threadIdx.x == 0) {
        int tag = s_lasttag;
        tags[len - 1] = (uint8_t)tag;
        for (int l = len - 2; l >= 0; --l) {
            tag = (int)hist8[(l + 1) * 16 + tag];
            tags[l] = (uint8_t)tag;
        }
    }
    __syncthreads();

    // =============================== write out ===============================
    float* ot = out + (size_t)b * Ln;
    for (int k = threadIdx.x; k < Ln; k += 256)
        ot[k] = (k < len) ? (float)tags[k] : 0.f;
    if (threadIdx.x == 0) out[(size_t)Bn * Ln + b] = s_best;
}

// ---------------------------------------------------------------------------
extern "C" void kernel_launch(void* const* d_in, const int* in_sizes, int n_in,
                              void* d_out, int out_size)
{
    const float* x    = (const float*)d_in[0];  // encoder_output [B,L,H2]
    const void*  mask = d_in[1];                // mask [B,L]
    const float* W    = (const float*)d_in[2];  // [T,H2]
    const float* bias = (const float*)d_in[3];  // [T]
    const float* st   = (const float*)d_in[4];  // start_transitions [T]
    const float* en   = (const float*)d_in[5];  // end_transitions [T]
    const float* tr   = (const float*)d_in[6];  // transitions [T,T]
    float* out = (float*)d_out;                 // tags [B*L] then best_score [B]

    cudaFuncSetAttribute(fused_kernel,
                         cudaFuncAttributeMaxDynamicSharedMemorySize, DYN_BYTES);
    fused_kernel<<<Bn, 256, DYN_BYTES>>>(x, mask, W, bias, st, en, tr, out);
}